// round 3
// baseline (speedup 1.0000x reference)
#include <cuda_runtime.h>

// ---------------------------------------------------------------------------
// WindowAttention fused kernel (fp32 baseline)
//   B=4096 windows, N=64 tokens, DIM=192, HEADS=6, HEAD_DIM=32
//   One CTA per window, 256 threads, everything staged in SMEM.
// ---------------------------------------------------------------------------

#define N_TOK     64
#define DIM       192
#define HEADS     6
#define HD        32
#define SCALE_F   0.17677669529663687f   // 32^-0.5

#define QKV_STRIDE 196   // 192 + 4 pad (avoid bank-aligned row stride)
#define SS_STRIDE  68    // 64 + 4 pad
#define WT_STRIDE  68    // transposed weight tile: wt[k][c], 96 x 64 (+pad)

// smem (floats):
//   qs : 64*196 = 12544
//   ks : 64*196 = 12544
//   vs : 64*196 = 12544
//   xs : 64*192 = 12288   (raw x; reused as score buffer ss[64*68])
//   wt : 96*68  =  6528
// total 56448 floats = 225792 bytes
#define SMEM_FLOATS (3 * N_TOK * QKV_STRIDE + N_TOK * DIM + 96 * WT_STRIDE)
#define SMEM_BYTES  (SMEM_FLOATS * 4)

__global__ void __launch_bounds__(256, 1)
winattn_kernel(const float* __restrict__ x,
               const float* __restrict__ qkv_w,
               const float* __restrict__ qkv_b,
               const float* __restrict__ proj_w,
               const float* __restrict__ proj_b,
               const float* __restrict__ bias_table,
               const int*   __restrict__ rel_idx,
               float*       __restrict__ out)
{
    extern __shared__ float sm[];
    float* qs = sm;
    float* ks = qs + N_TOK * QKV_STRIDE;
    float* vs = ks + N_TOK * QKV_STRIDE;
    float* xs = vs + N_TOK * QKV_STRIDE;   // 64*192
    float* wt = xs + N_TOK * DIM;          // 96*68, transposed weight tile
    float* ss = xs;                        // reuse xs as scores after GEMM

    const int tid = threadIdx.x;
    const int tc  = tid & 15;        // column-lane 0..15
    const int tn  = tid >> 4;        // row-group  0..15
    const int n0  = tn * 4;
    const int b   = blockIdx.x;

    // ---------------- phase 1: load x[b] into smem (coalesced float4) ------
    {
        const float4* xg  = (const float4*)(x + (size_t)b * N_TOK * DIM);
        float4*       xs4 = (float4*)xs;
        #pragma unroll
        for (int j = 0; j < 12; j++)
            xs4[tid + 256 * j] = xg[tid + 256 * j];
    }
    __syncthreads();

    // ---------------- phase 2: qkv = x @ qkv_w^T + b  ----------------------
    // out channels 0..575 processed in 9 chunks of 64; K split in two 96-halves
    for (int cc = 0; cc < 9; cc++) {
        float acc[4][4] = {};
        for (int kh = 0; kh < 2; kh++) {
            // stage W[cc*64 .. +64][kh*96 .. +96] transposed into wt[k][c]
            #pragma unroll
            for (int j = 0; j < 6; j++) {
                int idx = tid + 256 * j;          // 0..1535 = 64 rows * 24 f4
                int r  = idx / 24;
                int q4 = idx % 24;
                float4 w = *(const float4*)(qkv_w + (size_t)(cc * 64 + r) * DIM
                                            + kh * 96 + q4 * 4);
                wt[(q4 * 4 + 0) * WT_STRIDE + r] = w.x;
                wt[(q4 * 4 + 1) * WT_STRIDE + r] = w.y;
                wt[(q4 * 4 + 2) * WT_STRIDE + r] = w.z;
                wt[(q4 * 4 + 3) * WT_STRIDE + r] = w.w;
            }
            __syncthreads();

            const float* xbase = xs + kh * 96;
            #pragma unroll 4
            for (int kk = 0; kk < 96; kk += 4) {
                float4 w0 = *(const float4*)(wt + (kk + 0) * WT_STRIDE + tc * 4);
                float4 w1 = *(const float4*)(wt + (kk + 1) * WT_STRIDE + tc * 4);
                float4 w2 = *(const float4*)(wt + (kk + 2) * WT_STRIDE + tc * 4);
                float4 w3 = *(const float4*)(wt + (kk + 3) * WT_STRIDE + tc * 4);
                #pragma unroll
                for (int i = 0; i < 4; i++) {
                    float4 xv = *(const float4*)(xbase + (n0 + i) * DIM + kk);
                    acc[i][0] += xv.x*w0.x + xv.y*w1.x + xv.z*w2.x + xv.w*w3.x;
                    acc[i][1] += xv.x*w0.y + xv.y*w1.y + xv.z*w2.y + xv.w*w3.y;
                    acc[i][2] += xv.x*w0.z + xv.y*w1.z + xv.z*w2.z + xv.w*w3.z;
                    acc[i][3] += xv.x*w0.w + xv.y*w1.w + xv.z*w2.w + xv.w*w3.w;
                }
            }
            __syncthreads();
        }
        // writeback chunk (64 channels map entirely to one of q/k/v)
        float* dst; int cofs; float mul;
        if (cc < 3)      { dst = qs; cofs = cc * 64;       mul = SCALE_F; }
        else if (cc < 6) { dst = ks; cofs = (cc - 3) * 64; mul = 1.0f;    }
        else             { dst = vs; cofs = (cc - 6) * 64; mul = 1.0f;    }
        int cg = cc * 64 + tc * 4;
        float4 bv = *(const float4*)(qkv_b + cg);
        #pragma unroll
        for (int i = 0; i < 4; i++) {
            float4 r;
            r.x = (acc[i][0] + bv.x) * mul;
            r.y = (acc[i][1] + bv.y) * mul;
            r.z = (acc[i][2] + bv.z) * mul;
            r.w = (acc[i][3] + bv.w) * mul;
            *(float4*)(dst + (n0 + i) * QKV_STRIDE + cofs + tc * 4) = r;
        }
    }
    __syncthreads();

    // ---------------- phase 3: per-head attention ---------------------------
    for (int h = 0; h < HEADS; h++) {
        // S[n][m] = q_h[n] . k_h[m] + bias(h,n,m)   (q already pre-scaled)
        {
            float acc[4][4] = {};
            const float* qh = qs + h * HD;
            const float* kk_ = ks + h * HD;
            #pragma unroll
            for (int dd = 0; dd < HD; dd += 4) {
                float4 kv0 = *(const float4*)(kk_ + (tc +  0) * QKV_STRIDE + dd);
                float4 kv1 = *(const float4*)(kk_ + (tc + 16) * QKV_STRIDE + dd);
                float4 kv2 = *(const float4*)(kk_ + (tc + 32) * QKV_STRIDE + dd);
                float4 kv3 = *(const float4*)(kk_ + (tc + 48) * QKV_STRIDE + dd);
                #pragma unroll
                for (int i = 0; i < 4; i++) {
                    float4 qv = *(const float4*)(qh + (n0 + i) * QKV_STRIDE + dd);
                    acc[i][0] += qv.x*kv0.x + qv.y*kv0.y + qv.z*kv0.z + qv.w*kv0.w;
                    acc[i][1] += qv.x*kv1.x + qv.y*kv1.y + qv.z*kv1.z + qv.w*kv1.w;
                    acc[i][2] += qv.x*kv2.x + qv.y*kv2.y + qv.z*kv2.z + qv.w*kv2.w;
                    acc[i][3] += qv.x*kv3.x + qv.y*kv3.y + qv.z*kv3.z + qv.w*kv3.w;
                }
            }
            #pragma unroll
            for (int i = 0; i < 4; i++) {
                #pragma unroll
                for (int j = 0; j < 4; j++) {
                    int m = tc + 16 * j;
                    int ridx = rel_idx[(n0 + i) * N_TOK + m];
                    ss[(n0 + i) * SS_STRIDE + m] =
                        acc[i][j] + bias_table[ridx * HEADS + h];
                }
            }
        }
        __syncthreads();

        // softmax rows: warp w handles rows w, w+8, ...
        {
            int wid  = tid >> 5;
            int lane = tid & 31;
            for (int r = wid; r < N_TOK; r += 8) {
                float e0 = ss[r * SS_STRIDE + lane];
                float e1 = ss[r * SS_STRIDE + lane + 32];
                float mx = fmaxf(e0, e1);
                #pragma unroll
                for (int o = 16; o > 0; o >>= 1)
                    mx = fmaxf(mx, __shfl_xor_sync(0xffffffffu, mx, o));
                float p0 = __expf(e0 - mx);
                float p1 = __expf(e1 - mx);
                float s = p0 + p1;
                #pragma unroll
                for (int o = 16; o > 0; o >>= 1)
                    s += __shfl_xor_sync(0xffffffffu, s, o);
                float inv = 1.0f / s;
                ss[r * SS_STRIDE + lane]      = p0 * inv;
                ss[r * SS_STRIDE + lane + 32] = p1 * inv;
            }
        }
        __syncthreads();

        // O_h = S @ v_h  (thread: 4 rows x 2 dims, d0 = 2*tc); overwrite q_h
        {
            float o0[4] = {}, o1[4] = {};
            const float* vh = vs + h * HD + tc * 2;
            #pragma unroll 4
            for (int mm = 0; mm < N_TOK; mm += 4) {
                float2 v0 = *(const float2*)(vh + (mm + 0) * QKV_STRIDE);
                float2 v1 = *(const float2*)(vh + (mm + 1) * QKV_STRIDE);
                float2 v2 = *(const float2*)(vh + (mm + 2) * QKV_STRIDE);
                float2 v3 = *(const float2*)(vh + (mm + 3) * QKV_STRIDE);
                #pragma unroll
                for (int i = 0; i < 4; i++) {
                    float4 sv = *(const float4*)(ss + (n0 + i) * SS_STRIDE + mm);
                    o0[i] += sv.x*v0.x + sv.y*v1.x + sv.z*v2.x + sv.w*v3.x;
                    o1[i] += sv.x*v0.y + sv.y*v1.y + sv.z*v2.y + sv.w*v3.y;
                }
            }
            #pragma unroll
            for (int i = 0; i < 4; i++)
                *(float2*)(qs + (n0 + i) * QKV_STRIDE + h * HD + tc * 2) =
                    make_float2(o0[i], o1[i]);
        }
        __syncthreads();
    }

    // ---------------- phase 4: out = O @ proj_w^T + proj_b -----------------
    for (int cc = 0; cc < 3; cc++) {
        float acc[4][4] = {};
        for (int kh = 0; kh < 2; kh++) {
            #pragma unroll
            for (int j = 0; j < 6; j++) {
                int idx = tid + 256 * j;
                int r  = idx / 24;
                int q4 = idx % 24;
                float4 w = *(const float4*)(proj_w + (size_t)(cc * 64 + r) * DIM
                                            + kh * 96 + q4 * 4);
                wt[(q4 * 4 + 0) * WT_STRIDE + r] = w.x;
                wt[(q4 * 4 + 1) * WT_STRIDE + r] = w.y;
                wt[(q4 * 4 + 2) * WT_STRIDE + r] = w.z;
                wt[(q4 * 4 + 3) * WT_STRIDE + r] = w.w;
            }
            __syncthreads();

            const float* obase = qs + kh * 96;
            #pragma unroll 4
            for (int kk = 0; kk < 96; kk += 4) {
                float4 w0 = *(const float4*)(wt + (kk + 0) * WT_STRIDE + tc * 4);
                float4 w1 = *(const float4*)(wt + (kk + 1) * WT_STRIDE + tc * 4);
                float4 w2 = *(const float4*)(wt + (kk + 2) * WT_STRIDE + tc * 4);
                float4 w3 = *(const float4*)(wt + (kk + 3) * WT_STRIDE + tc * 4);
                #pragma unroll
                for (int i = 0; i < 4; i++) {
                    float4 ov = *(const float4*)(obase + (n0 + i) * QKV_STRIDE + kk);
                    acc[i][0] += ov.x*w0.x + ov.y*w1.x + ov.z*w2.x + ov.w*w3.x;
                    acc[i][1] += ov.x*w0.y + ov.y*w1.y + ov.z*w2.y + ov.w*w3.y;
                    acc[i][2] += ov.x*w0.z + ov.y*w1.z + ov.z*w2.z + ov.w*w3.z;
                    acc[i][3] += ov.x*w0.w + ov.y*w1.w + ov.z*w2.w + ov.w*w3.w;
                }
            }
            __syncthreads();
        }
        int c0 = cc * 64 + tc * 4;
        float4 bv = *(const float4*)(proj_b + c0);
        #pragma unroll
        for (int i = 0; i < 4; i++) {
            float4 r;
            r.x = acc[i][0] + bv.x;
            r.y = acc[i][1] + bv.y;
            r.z = acc[i][2] + bv.z;
            r.w = acc[i][3] + bv.w;
            *(float4*)(out + (size_t)b * N_TOK * DIM + (n0 + i) * DIM + c0) = r;
        }
    }
}

extern "C" void kernel_launch(void* const* d_in, const int* in_sizes, int n_in,
                              void* d_out, int out_size)
{
    const float* x          = (const float*)d_in[0];
    const float* qkv_w      = (const float*)d_in[1];
    const float* qkv_b      = (const float*)d_in[2];
    const float* proj_w     = (const float*)d_in[3];
    const float* proj_b     = (const float*)d_in[4];
    const float* bias_table = (const float*)d_in[5];
    const int*   rel_idx    = (const int*)d_in[6];
    float* out = (float*)d_out;

    int B = in_sizes[0] / (N_TOK * DIM);   // 4096

    cudaFuncSetAttribute(winattn_kernel,
                         cudaFuncAttributeMaxDynamicSharedMemorySize, SMEM_BYTES);

    winattn_kernel<<<B, 256, SMEM_BYTES>>>(x, qkv_w, qkv_b, proj_w, proj_b,
                                           bias_table, rel_idx, out);
}

// round 7
// speedup vs baseline: 3.7833x; 3.7833x over previous
#include <cuda_runtime.h>
#include <cuda_fp16.h>
#include <cstdint>

// ===========================================================================
// WindowAttention fused, HMMA (mma.sync m16n8k16 f16 -> f32)
//   1 window per CTA (64 tokens x 192 dim), 256 threads / 8 warps.
// ===========================================================================

#define DIMC    192
#define SCALE_F 0.17677669529663687f

// ---- smem byte offsets ----------------------------------------------------
// fp16 row stride 200 halfs (400B, ==16 mod 128 -> ldmatrix conflict-free)
// vt/psh stride 72 halfs (144B, ==16 mod 128)
#define QS_OFF   0          // q / later O : 64 x 200 halfs = 25600 B
#define KS_OFF   25600      // k           : 64 x 200
#define VT_OFF   51200      // v^T         : 192 x 72 halfs = 27648 B
#define XS_OFF   78848      // x (also ps fp32 64x72 = 18432 B alias)
#define WB_OFF   104448     // weight chunks: 2 x (64 x 200 halfs = 25600 B)
#define WB_SZ    25600      //   (wb0 also aliased as psh fp16 64x72)
#define BIAS_OFF 155648     // bias_table fp32: 1350 * 4 = 5400 B
#define REL_OFF  161048     // rel_idx u8: 4096 B
#define SM_TOTAL 165152

// prepped fp16 weights (plain row-major [out_ch][k])
__device__ __half g_wq[576 * 192];
__device__ __half g_wp[192 * 192];

// ---------------------------------------------------------------------------
__device__ __forceinline__ uint32_t s2u(const void* p) {
    uint32_t a;
    asm("{ .reg .u64 t; cvta.to.shared.u64 t, %1; cvt.u32.u64 %0, t; }"
        : "=r"(a) : "l"(p));
    return a;
}

__device__ __forceinline__ void ldsm4(uint32_t r[4], uint32_t a) {
    asm volatile("ldmatrix.sync.aligned.m8n8.x4.shared.b16 {%0,%1,%2,%3}, [%4];"
        : "=r"(r[0]), "=r"(r[1]), "=r"(r[2]), "=r"(r[3]) : "r"(a));
}

__device__ __forceinline__ void hmma(float c[4], const uint32_t a[4],
                                     uint32_t b0, uint32_t b1) {
    asm volatile(
        "mma.sync.aligned.m16n8k16.row.col.f32.f16.f16.f32 "
        "{%0,%1,%2,%3}, {%4,%5,%6,%7}, {%8,%9}, {%0,%1,%2,%3};"
        : "+f"(c[0]), "+f"(c[1]), "+f"(c[2]), "+f"(c[3])
        : "r"(a[0]), "r"(a[1]), "r"(a[2]), "r"(a[3]), "r"(b0), "r"(b1));
}

#define CP16(dst, src) asm volatile("cp.async.cg.shared.global [%0], [%1], 16;" :: "r"(dst), "l"(src))
#define CPCOMMIT()     asm volatile("cp.async.commit_group;" ::: "memory")
#define CPWAIT0()      asm volatile("cp.async.wait_group 0;" ::: "memory")

// stage one 64x192 fp16 weight chunk (row stride 400B in smem)
__device__ __forceinline__ void prefetch_chunk(uint32_t wbAddr, const __half* src,
                                               int tid) {
    #pragma unroll
    for (int i = 0; i < 6; i++) {
        int idx = tid + 256 * i;          // 0..1535 = 64 rows * 24 segs
        int row = idx / 24, seg = idx % 24;
        CP16(wbAddr + row * 400 + seg * 16,
             (const char*)src + row * 384 + seg * 16);
    }
}

// K=192 GEMM: warp computes m16 x n32; A rows stride 400B, B rows stride 400B
__device__ __forceinline__ void gemm192(uint32_t aBase, uint32_t bBase, int lane,
                                        float acc[4][4]) {
    uint32_t aRow = aBase + (lane & 15) * 400 + ((lane >> 4) << 4);
    uint32_t bRow = bBase + (((lane >> 4) << 3) + (lane & 7)) * 400
                  + (((lane >> 3) & 1) << 4);
    #pragma unroll
    for (int k = 0; k < 12; k++) {
        uint32_t a[4];  ldsm4(a,  aRow + k * 32);
        uint32_t b0[4]; ldsm4(b0, bRow + k * 32);
        uint32_t b1[4]; ldsm4(b1, bRow + 16 * 400 + k * 32);
        hmma(acc[0], a, b0[0], b0[1]);
        hmma(acc[1], a, b0[2], b0[3]);
        hmma(acc[2], a, b1[0], b1[1]);
        hmma(acc[3], a, b1[2], b1[3]);
    }
}

// ---------------------------------------------------------------------------
__global__ void wa_prep(const float* __restrict__ qkv_w,
                        const float* __restrict__ proj_w)
{
    int i = blockIdx.x * blockDim.x + threadIdx.x;
    if (i < 576 * 192) g_wq[i] = __float2half_rn(qkv_w[i]);
    if (i < 192 * 192) g_wp[i] = __float2half_rn(proj_w[i]);
}

// ---------------------------------------------------------------------------
__global__ void __launch_bounds__(256, 1)
wa_main(const float* __restrict__ x,
        const float* __restrict__ qkv_b,
        const float* __restrict__ proj_b,
        const float* __restrict__ bias_table,
        const int*   __restrict__ rel_idx,
        float*       __restrict__ out)
{
    extern __shared__ __align__(16) char sm[];
    const uint32_t smb = s2u(sm);
    const int tid  = threadIdx.x;
    const int wid  = tid >> 5;
    const int lane = tid & 31;
    const int m0   = (wid & 3) * 16;     // warp m-tile base
    const int ng   = wid >> 2;           // warp n-group (0/1)
    const int m_r  = m0 + (lane >> 2);
    const int n_b  = ng * 32 + 2 * (lane & 3);

    // prefetch qkv chunk 0 first (overlaps staging)
    prefetch_chunk(smb + WB_OFF, g_wq, tid);
    CPCOMMIT();

    // stage x -> fp16 xs[64][200]   (4 floats -> 8 BYTES fp16: seg stride 8!)
    {
        const float4* xg = (const float4*)(x + (size_t)blockIdx.x * 64 * DIMC);
        #pragma unroll
        for (int i = 0; i < 12; i++) {
            int idx = tid + 256 * i;           // 3072 float4 = 64 rows * 48
            int r = idx / 48, c4 = idx % 48;
            float4 v = xg[idx];
            __half2* d = (__half2*)(sm + XS_OFF + r * 400 + c4 * 8);
            d[0] = __floats2half2_rn(v.x, v.y);
            d[1] = __floats2half2_rn(v.z, v.w);
        }
    }
    for (int i = tid; i < 1350; i += 256)
        ((float*)(sm + BIAS_OFF))[i] = bias_table[i];
    for (int i = tid; i < 4096; i += 256)
        ((uint8_t*)(sm + REL_OFF))[i] = (uint8_t)rel_idx[i];
    __syncthreads();

    // ================= phase 1: qkv GEMM, 9 chunks of 64 channels ==========
    for (int cc = 0; cc < 9; cc++) {
        CPWAIT0();
        __syncthreads();                       // chunk cc visible to all
        const __half* nxt = (cc < 8) ? (g_wq + (cc + 1) * 64 * 192) : g_wp;
        prefetch_chunk(smb + WB_OFF + ((cc + 1) & 1) * WB_SZ, nxt, tid);
        CPCOMMIT();

        float acc[4][4] = {};
        gemm192(smb + XS_OFF + m0 * 400,
                smb + WB_OFF + (cc & 1) * WB_SZ + ng * 32 * 400, lane, acc);

        if (cc < 3) {                          // Q (pre-scaled)
            int c0 = cc * 64;
            #pragma unroll
            for (int jj = 0; jj < 4; jj++) {
                int n = n_b + 8 * jj, col = c0 + n;
                float b0 = __ldg(qkv_b + col), b1 = __ldg(qkv_b + col + 1);
                *(__half2*)(sm + QS_OFF + m_r * 400 + col * 2) =
                    __floats2half2_rn((acc[jj][0] + b0) * SCALE_F,
                                      (acc[jj][1] + b1) * SCALE_F);
                *(__half2*)(sm + QS_OFF + (m_r + 8) * 400 + col * 2) =
                    __floats2half2_rn((acc[jj][2] + b0) * SCALE_F,
                                      (acc[jj][3] + b1) * SCALE_F);
            }
        } else if (cc < 6) {                   // K
            int c0 = (cc - 3) * 64;
            #pragma unroll
            for (int jj = 0; jj < 4; jj++) {
                int n = n_b + 8 * jj, col = c0 + n;
                float b0 = __ldg(qkv_b + 192 + col), b1 = __ldg(qkv_b + 192 + col + 1);
                *(__half2*)(sm + KS_OFF + m_r * 400 + col * 2) =
                    __floats2half2_rn(acc[jj][0] + b0, acc[jj][1] + b1);
                *(__half2*)(sm + KS_OFF + (m_r + 8) * 400 + col * 2) =
                    __floats2half2_rn(acc[jj][2] + b0, acc[jj][3] + b1);
            }
        } else {                               // V -> vt[d][tok]
            int c0 = (cc - 6) * 64;
            __half* vt = (__half*)(sm + VT_OFF);
            #pragma unroll
            for (int jj = 0; jj < 4; jj++) {
                int d = c0 + n_b + 8 * jj;
                float b0 = __ldg(qkv_b + 384 + d), b1 = __ldg(qkv_b + 384 + d + 1);
                vt[d * 72 + m_r]           = __float2half_rn(acc[jj][0] + b0);
                vt[(d + 1) * 72 + m_r]     = __float2half_rn(acc[jj][1] + b1);
                vt[d * 72 + m_r + 8]       = __float2half_rn(acc[jj][2] + b0);
                vt[(d + 1) * 72 + m_r + 8] = __float2half_rn(acc[jj][3] + b1);
            }
        }
    }
    __syncthreads();

    // ================= phase 2: attention, 6 heads ==========================
    float* ps   = (float*)(sm + XS_OFF);       // scores fp32 64x72
    __half* psh = (__half*)(sm + WB_OFF);      // probs fp16 64x72 (aliases wb0)

    for (int h = 0; h < 6; h++) {
        // ---- S = Q_h K_h^T ----
        {
            float sc[4][4] = {};
            uint32_t aRow = smb + QS_OFF + (m0 + (lane & 15)) * 400 + h * 64
                          + ((lane >> 4) << 4);
            uint32_t bRow = smb + KS_OFF
                          + (ng * 32 + ((lane >> 4) << 3) + (lane & 7)) * 400
                          + h * 64 + (((lane >> 3) & 1) << 4);
            #pragma unroll
            for (int k = 0; k < 2; k++) {
                uint32_t a[4];  ldsm4(a,  aRow + k * 32);
                uint32_t b0[4]; ldsm4(b0, bRow + k * 32);
                uint32_t b1[4]; ldsm4(b1, bRow + 16 * 400 + k * 32);
                hmma(sc[0], a, b0[0], b0[1]);
                hmma(sc[1], a, b0[2], b0[3]);
                hmma(sc[2], a, b1[0], b1[1]);
                hmma(sc[3], a, b1[2], b1[3]);
            }
            #pragma unroll
            for (int jj = 0; jj < 4; jj++) {
                int n = n_b + 8 * jj;
                ps[m_r * 72 + n]           = sc[jj][0];
                ps[m_r * 72 + n + 1]       = sc[jj][1];
                ps[(m_r + 8) * 72 + n]     = sc[jj][2];
                ps[(m_r + 8) * 72 + n + 1] = sc[jj][3];
            }
        }
        __syncthreads();

        // ---- bias + softmax (warp per row, 8 rows/warp) ----
        {
            const uint8_t* rl = (const uint8_t*)(sm + REL_OFF);
            const float*   bt = (const float*)(sm + BIAS_OFF);
            for (int r = wid; r < 64; r += 8) {
                float e0 = ps[r * 72 + lane]      + bt[rl[r * 64 + lane] * 6 + h];
                float e1 = ps[r * 72 + lane + 32] + bt[rl[r * 64 + lane + 32] * 6 + h];
                float mx = fmaxf(e0, e1);
                #pragma unroll
                for (int o = 16; o > 0; o >>= 1)
                    mx = fmaxf(mx, __shfl_xor_sync(0xffffffffu, mx, o));
                float p0 = __expf(e0 - mx), p1 = __expf(e1 - mx);
                float s = p0 + p1;
                #pragma unroll
                for (int o = 16; o > 0; o >>= 1)
                    s += __shfl_xor_sync(0xffffffffu, s, o);
                float inv = 1.0f / s;
                psh[r * 72 + lane]      = __float2half_rn(p0 * inv);
                psh[r * 72 + lane + 32] = __float2half_rn(p1 * inv);
            }
        }
        __syncthreads();

        // ---- O_h = P V_h (warp: m16 x n16), overwrite Q slice h ----
        {
            float oc[2][4] = {};
            int nh = ng * 16;
            uint32_t aRow = smb + WB_OFF + (m0 + (lane & 15)) * 144
                          + ((lane >> 4) << 4);
            uint32_t bRow = smb + VT_OFF
                          + (h * 32 + nh + ((lane >> 4) << 3) + (lane & 7)) * 144
                          + (((lane >> 3) & 1) << 4);
            #pragma unroll
            for (int k = 0; k < 4; k++) {
                uint32_t a[4];  ldsm4(a,  aRow + k * 32);
                uint32_t bb[4]; ldsm4(bb, bRow + k * 32);
                hmma(oc[0], a, bb[0], bb[1]);
                hmma(oc[1], a, bb[2], bb[3]);
            }
            #pragma unroll
            for (int jj = 0; jj < 2; jj++) {
                int col = h * 32 + nh + 2 * (lane & 3) + 8 * jj;
                *(__half2*)(sm + QS_OFF + m_r * 400 + col * 2) =
                    __floats2half2_rn(oc[jj][0], oc[jj][1]);
                *(__half2*)(sm + QS_OFF + (m_r + 8) * 400 + col * 2) =
                    __floats2half2_rn(oc[jj][2], oc[jj][3]);
            }
        }
        // no barrier needed before next head's S (disjoint QS columns);
        // next S's ps writes are safe: softmax readers passed pre-PV barrier
    }
    __syncthreads();

    // ================= phase 3: proj GEMM, 3 chunks of 64 ==================
    for (int g = 0; g < 3; g++) {
        CPWAIT0();
        __syncthreads();                       // chunk ready + psh readers done
        if (g < 2) {
            prefetch_chunk(smb + WB_OFF + (g & 1) * WB_SZ,
                           g_wp + (g + 1) * 64 * 192, tid);
            CPCOMMIT();
        }
        float acc[4][4] = {};
        gemm192(smb + QS_OFF + m0 * 400,
                smb + WB_OFF + ((9 + g) & 1) * WB_SZ + ng * 32 * 400, lane, acc);

        int c0 = g * 64;
        size_t gbase = (size_t)blockIdx.x * 64;
        #pragma unroll
        for (int jj = 0; jj < 4; jj++) {
            int n = n_b + 8 * jj, col = c0 + n;
            float b0 = __ldg(proj_b + col), b1 = __ldg(proj_b + col + 1);
            float2 r0 = make_float2(acc[jj][0] + b0, acc[jj][1] + b1);
            float2 r1 = make_float2(acc[jj][2] + b0, acc[jj][3] + b1);
            *(float2*)(out + (gbase + m_r) * 192 + col)     = r0;
            *(float2*)(out + (gbase + m_r + 8) * 192 + col) = r1;
        }
        __syncthreads();                       // all reads of wb done before reuse
    }
}

// ---------------------------------------------------------------------------
extern "C" void kernel_launch(void* const* d_in, const int* in_sizes, int n_in,
                              void* d_out, int out_size)
{
    const float* x          = (const float*)d_in[0];
    const float* qkv_w      = (const float*)d_in[1];
    const float* qkv_b      = (const float*)d_in[2];
    const float* proj_w     = (const float*)d_in[3];
    const float* proj_b     = (const float*)d_in[4];
    const float* bias_table = (const float*)d_in[5];
    const int*   rel_idx    = (const int*)d_in[6];
    float* out = (float*)d_out;
    (void)n_in; (void)out_size;

    int B = in_sizes[0] / (64 * DIMC);    // 4096 windows

    cudaFuncSetAttribute(wa_main, cudaFuncAttributeMaxDynamicSharedMemorySize,
                         SM_TOTAL);

    wa_prep<<<432, 256>>>(qkv_w, proj_w);
    wa_main<<<B, 256, SM_TOTAL>>>(x, qkv_b, proj_b, bias_table, rel_idx, out);
}

// round 8
// speedup vs baseline: 5.6224x; 1.4861x over previous
#include <cuda_runtime.h>
#include <cuda_fp16.h>
#include <cstdint>

// ===========================================================================
// WindowAttention fused, HMMA (mma.sync m16n8k16 f16 -> f32)
//   1 window per CTA, 256 threads / 8 warps, 2 CTAs per SM.
//   A-operands register-cached; weight chunks 32ch double-buffered cp.async.
// ===========================================================================

#define DIMC    192
#define SCALE_F 0.17677669529663687f

// ---- smem byte offsets ----------------------------------------------------
// fp16 row stride 400B (==16 mod 128 -> ldmatrix conflict-free); vt/psh 144B
#define QS_OFF   0          // X staging, then Q / O : 64 x 200 halfs = 25600 B
#define KS_OFF   25600      // K : 25600 B
#define VT_OFF   51200      // V^T : 192 x 72 halfs = 27648 B
#define WBU_OFF  78848      // phase1/3: 2 x 12800 weight bufs; phase2: ps+psh
#define WB_SZ    12800
#define PS_OFF   WBU_OFF            // scores fp32 64 x 72 = 18432 B
#define PSH_OFF  (WBU_OFF + 18432)  // probs  fp16 64 x 72 =  9216 B
#define BIAS_OFF 106496     // bias_table fp16: 2700 B
#define REL_OFF  109200     // rel_idx u8: 4096 B
#define SM_TOTAL 113296

// prepped fp16 weights (row-major [out_ch][k])
__device__ __half g_wq[576 * 192];
__device__ __half g_wp[192 * 192];

// ---------------------------------------------------------------------------
__device__ __forceinline__ uint32_t s2u(const void* p) {
    uint32_t a;
    asm("{ .reg .u64 t; cvta.to.shared.u64 t, %1; cvt.u32.u64 %0, t; }"
        : "=r"(a) : "l"(p));
    return a;
}

__device__ __forceinline__ void ldsm4(uint32_t r[4], uint32_t a) {
    asm volatile("ldmatrix.sync.aligned.m8n8.x4.shared.b16 {%0,%1,%2,%3}, [%4];"
        : "=r"(r[0]), "=r"(r[1]), "=r"(r[2]), "=r"(r[3]) : "r"(a));
}

__device__ __forceinline__ void hmma(float c[4], const uint32_t a[4],
                                     uint32_t b0, uint32_t b1) {
    asm volatile(
        "mma.sync.aligned.m16n8k16.row.col.f32.f16.f16.f32 "
        "{%0,%1,%2,%3}, {%4,%5,%6,%7}, {%8,%9}, {%0,%1,%2,%3};"
        : "+f"(c[0]), "+f"(c[1]), "+f"(c[2]), "+f"(c[3])
        : "r"(a[0]), "r"(a[1]), "r"(a[2]), "r"(a[3]), "r"(b0), "r"(b1));
}

#define CP16(dst, src) asm volatile("cp.async.cg.shared.global [%0], [%1], 16;" :: "r"(dst), "l"(src))
#define CPCOMMIT()     asm volatile("cp.async.commit_group;" ::: "memory")
#define CPWAIT0()      asm volatile("cp.async.wait_group 0;" ::: "memory")

// stage one 32x192 fp16 weight chunk (row stride 400B in smem)
__device__ __forceinline__ void prefetch32(uint32_t wbAddr, const __half* src,
                                           int tid) {
    #pragma unroll
    for (int i = 0; i < 3; i++) {
        int idx = tid + 256 * i;          // 0..767 = 32 rows * 24 segs
        int row = idx / 24, seg = idx % 24;
        CP16(wbAddr + row * 400 + seg * 16,
             (const char*)src + row * 384 + seg * 16);
    }
}

// ---------------------------------------------------------------------------
__global__ void wa_prep(const float* __restrict__ qkv_w,
                        const float* __restrict__ proj_w)
{
    int i = blockIdx.x * blockDim.x + threadIdx.x;
    if (i < 576 * 192) g_wq[i] = __float2half_rn(qkv_w[i]);
    if (i < 192 * 192) g_wp[i] = __float2half_rn(proj_w[i]);
}

// ---------------------------------------------------------------------------
__global__ void __launch_bounds__(256, 2)
wa_main(const float* __restrict__ x,
        const float* __restrict__ qkv_b,
        const float* __restrict__ proj_b,
        const float* __restrict__ bias_table,
        const int*   __restrict__ rel_idx,
        float*       __restrict__ out)
{
    extern __shared__ __align__(16) char sm[];
    const uint32_t smb = s2u(sm);
    const int tid  = threadIdx.x;
    const int wid  = tid >> 5;
    const int lane = tid & 31;
    const int m0   = (wid & 3) * 16;     // warp m-tile base
    const int ng   = wid >> 2;           // warp n-group (0/1)
    const int m_r  = m0 + (lane >> 2);
    const int n_c  = 2 * (lane & 3);     // col-pair within n8 block

    // A-fragment ldmatrix address (m16 tile, 16B k-split), reused ph1/ph3
    const uint32_t aRowQ = smb + QS_OFF + (m0 + (lane & 15)) * 400
                         + ((lane >> 4) << 4);
    // B-row base pattern for n16 (16 rows) ldmatrix.x4
    const uint32_t bSel  = (ng * 16 + ((lane >> 4) << 3) + (lane & 7)) * 400
                         + (((lane >> 3) & 1) << 4);

    prefetch32(smb + WBU_OFF, g_wq, tid);   // qkv chunk 0
    CPCOMMIT();

    // stage x -> fp16 in QS region (stride 400B)
    {
        const float4* xg = (const float4*)(x + (size_t)blockIdx.x * 64 * DIMC);
        #pragma unroll
        for (int i = 0; i < 12; i++) {
            int idx = tid + 256 * i;           // 3072 float4 = 64 rows * 48
            int r = idx / 48, c4 = idx % 48;
            float4 v = xg[idx];
            __half2* d = (__half2*)(sm + QS_OFF + r * 400 + c4 * 8);
            d[0] = __floats2half2_rn(v.x, v.y);
            d[1] = __floats2half2_rn(v.z, v.w);
        }
    }
    for (int i = tid; i < 1350; i += 256)
        ((__half*)(sm + BIAS_OFF))[i] = __float2half_rn(bias_table[i]);
    for (int i = tid; i < 4096; i += 256)
        ((uint8_t*)(sm + REL_OFF))[i] = (uint8_t)rel_idx[i];
    __syncthreads();

    // cache X A-fragments in registers (k = 0..191 in 12 steps)
    uint32_t af[12][4];
    #pragma unroll
    for (int k = 0; k < 12; k++) ldsm4(af[k], aRowQ + k * 32);

    CPWAIT0();
    __syncthreads();     // chunk0 visible to all; all X reads complete

    // ================= phase 1: qkv GEMM, 18 chunks of 32 channels =========
    for (int cc = 0; cc < 18; cc++) {
        if (cc < 17) {
            prefetch32(smb + WBU_OFF + ((cc + 1) & 1) * WB_SZ,
                       g_wq + (cc + 1) * 32 * 192, tid);
            CPCOMMIT();
        }
        float acc[2][4] = {};
        uint32_t bRow = smb + WBU_OFF + (cc & 1) * WB_SZ + bSel;
        #pragma unroll
        for (int k = 0; k < 12; k++) {
            uint32_t b[4]; ldsm4(b, bRow + k * 32);
            hmma(acc[0], af[k], b[0], b[1]);
            hmma(acc[1], af[k], b[2], b[3]);
        }
        if (cc < 6) {                          // Q (pre-scaled)
            #pragma unroll
            for (int jj = 0; jj < 2; jj++) {
                int col = cc * 32 + ng * 16 + n_c + 8 * jj;
                float b0 = __ldg(qkv_b + col), b1 = __ldg(qkv_b + col + 1);
                *(__half2*)(sm + QS_OFF + m_r * 400 + col * 2) =
                    __floats2half2_rn((acc[jj][0] + b0) * SCALE_F,
                                      (acc[jj][1] + b1) * SCALE_F);
                *(__half2*)(sm + QS_OFF + (m_r + 8) * 400 + col * 2) =
                    __floats2half2_rn((acc[jj][2] + b0) * SCALE_F,
                                      (acc[jj][3] + b1) * SCALE_F);
            }
        } else if (cc < 12) {                  // K
            #pragma unroll
            for (int jj = 0; jj < 2; jj++) {
                int col = (cc - 6) * 32 + ng * 16 + n_c + 8 * jj;
                float b0 = __ldg(qkv_b + 192 + col), b1 = __ldg(qkv_b + 192 + col + 1);
                *(__half2*)(sm + KS_OFF + m_r * 400 + col * 2) =
                    __floats2half2_rn(acc[jj][0] + b0, acc[jj][1] + b1);
                *(__half2*)(sm + KS_OFF + (m_r + 8) * 400 + col * 2) =
                    __floats2half2_rn(acc[jj][2] + b0, acc[jj][3] + b1);
            }
        } else {                               // V -> vt[d][tok]
            __half* vt = (__half*)(sm + VT_OFF);
            #pragma unroll
            for (int jj = 0; jj < 2; jj++) {
                int d = (cc - 12) * 32 + ng * 16 + n_c + 8 * jj;
                float b0 = __ldg(qkv_b + 384 + d), b1 = __ldg(qkv_b + 384 + d + 1);
                vt[d * 72 + m_r]           = __float2half_rn(acc[jj][0] + b0);
                vt[(d + 1) * 72 + m_r]     = __float2half_rn(acc[jj][1] + b1);
                vt[d * 72 + m_r + 8]       = __float2half_rn(acc[jj][2] + b0);
                vt[(d + 1) * 72 + m_r + 8] = __float2half_rn(acc[jj][3] + b1);
            }
        }
        if (cc < 17) { CPWAIT0(); __syncthreads(); }
    }
    __syncthreads();     // cp.async pipeline empty; VT/QS/KS complete

    // ================= phase 2: attention, 6 heads ==========================
    float*  ps  = (float*)(sm + PS_OFF);
    __half* psh = (__half*)(sm + PSH_OFF);
    const int n_b2 = ng * 32 + n_c;

    for (int h = 0; h < 6; h++) {
        // ---- S = Q_h K_h^T (warp: m16 x n32) ----
        {
            float sc[4][4] = {};
            uint32_t aR = smb + QS_OFF + (m0 + (lane & 15)) * 400 + h * 64
                        + ((lane >> 4) << 4);
            uint32_t bR = smb + KS_OFF
                        + (ng * 32 + ((lane >> 4) << 3) + (lane & 7)) * 400
                        + h * 64 + (((lane >> 3) & 1) << 4);
            #pragma unroll
            for (int k = 0; k < 2; k++) {
                uint32_t a[4];  ldsm4(a,  aR + k * 32);
                uint32_t b0[4]; ldsm4(b0, bR + k * 32);
                uint32_t b1[4]; ldsm4(b1, bR + 16 * 400 + k * 32);
                hmma(sc[0], a, b0[0], b0[1]);
                hmma(sc[1], a, b0[2], b0[3]);
                hmma(sc[2], a, b1[0], b1[1]);
                hmma(sc[3], a, b1[2], b1[3]);
            }
            #pragma unroll
            for (int jj = 0; jj < 4; jj++) {
                int n = n_b2 + 8 * jj;
                ps[m_r * 72 + n]           = sc[jj][0];
                ps[m_r * 72 + n + 1]       = sc[jj][1];
                ps[(m_r + 8) * 72 + n]     = sc[jj][2];
                ps[(m_r + 8) * 72 + n + 1] = sc[jj][3];
            }
        }
        __syncthreads();

        // ---- bias + softmax (warp per row, 8 rows/warp) ----
        {
            const uint8_t* rl = (const uint8_t*)(sm + REL_OFF);
            const __half*  bt = (const __half*)(sm + BIAS_OFF);
            for (int r = wid; r < 64; r += 8) {
                float e0 = ps[r * 72 + lane]
                         + __half2float(bt[rl[r * 64 + lane] * 6 + h]);
                float e1 = ps[r * 72 + lane + 32]
                         + __half2float(bt[rl[r * 64 + lane + 32] * 6 + h]);
                float mx = fmaxf(e0, e1);
                #pragma unroll
                for (int o = 16; o > 0; o >>= 1)
                    mx = fmaxf(mx, __shfl_xor_sync(0xffffffffu, mx, o));
                float p0 = __expf(e0 - mx), p1 = __expf(e1 - mx);
                float s = p0 + p1;
                #pragma unroll
                for (int o = 16; o > 0; o >>= 1)
                    s += __shfl_xor_sync(0xffffffffu, s, o);
                float inv = 1.0f / s;
                psh[r * 72 + lane]      = __float2half_rn(p0 * inv);
                psh[r * 72 + lane + 32] = __float2half_rn(p1 * inv);
            }
        }
        __syncthreads();

        // ---- O_h = P V_h (warp: m16 x n16), overwrite Q slice h ----
        {
            float oc[2][4] = {};
            uint32_t aR = smb + PSH_OFF + (m0 + (lane & 15)) * 144
                        + ((lane >> 4) << 4);
            uint32_t bR = smb + VT_OFF
                        + (h * 32 + ng * 16 + ((lane >> 4) << 3) + (lane & 7)) * 144
                        + (((lane >> 3) & 1) << 4);
            #pragma unroll
            for (int k = 0; k < 4; k++) {
                uint32_t a[4];  ldsm4(a,  aR + k * 32);
                uint32_t bb[4]; ldsm4(bb, bR + k * 32);
                hmma(oc[0], a, bb[0], bb[1]);
                hmma(oc[1], a, bb[2], bb[3]);
            }
            #pragma unroll
            for (int jj = 0; jj < 2; jj++) {
                int col = h * 32 + ng * 16 + n_c + 8 * jj;
                *(__half2*)(sm + QS_OFF + m_r * 400 + col * 2) =
                    __floats2half2_rn(oc[jj][0], oc[jj][1]);
                *(__half2*)(sm + QS_OFF + (m_r + 8) * 400 + col * 2) =
                    __floats2half2_rn(oc[jj][2], oc[jj][3]);
            }
        }
        // next head's S reads disjoint QS cols; ps rewrite safe (post-sync)
    }
    __syncthreads();     // O complete; psh consumed -> WBU region free

    // ================= phase 3: proj GEMM, 6 chunks of 32 ==================
    prefetch32(smb + WBU_OFF, g_wp, tid);
    CPCOMMIT();
    #pragma unroll
    for (int k = 0; k < 12; k++) ldsm4(af[k], aRowQ + k * 32);   // O frags
    CPWAIT0();
    __syncthreads();

    const size_t gbase = (size_t)blockIdx.x * 64;
    for (int g = 0; g < 6; g++) {
        if (g < 5) {
            prefetch32(smb + WBU_OFF + ((g + 1) & 1) * WB_SZ,
                       g_wp + (g + 1) * 32 * 192, tid);
            CPCOMMIT();
        }
        float acc[2][4] = {};
        uint32_t bRow = smb + WBU_OFF + (g & 1) * WB_SZ + bSel;
        #pragma unroll
        for (int k = 0; k < 12; k++) {
            uint32_t b[4]; ldsm4(b, bRow + k * 32);
            hmma(acc[0], af[k], b[0], b[1]);
            hmma(acc[1], af[k], b[2], b[3]);
        }
        #pragma unroll
        for (int jj = 0; jj < 2; jj++) {
            int col = g * 32 + ng * 16 + n_c + 8 * jj;
            float b0 = __ldg(proj_b + col), b1 = __ldg(proj_b + col + 1);
            *(float2*)(out + (gbase + m_r) * 192 + col) =
                make_float2(acc[jj][0] + b0, acc[jj][1] + b1);
            *(float2*)(out + (gbase + m_r + 8) * 192 + col) =
                make_float2(acc[jj][2] + b0, acc[jj][3] + b1);
        }
        if (g < 5) { CPWAIT0(); __syncthreads(); }
    }
}

// ---------------------------------------------------------------------------
extern "C" void kernel_launch(void* const* d_in, const int* in_sizes, int n_in,
                              void* d_out, int out_size)
{
    const float* x          = (const float*)d_in[0];
    const float* qkv_w      = (const float*)d_in[1];
    const float* qkv_b      = (const float*)d_in[2];
    const float* proj_w     = (const float*)d_in[3];
    const float* proj_b     = (const float*)d_in[4];
    const float* bias_table = (const float*)d_in[5];
    const int*   rel_idx    = (const int*)d_in[6];
    float* out = (float*)d_out;
    (void)n_in; (void)out_size;

    int B = in_sizes[0] / (64 * DIMC);    // 4096 windows

    cudaFuncSetAttribute(wa_main, cudaFuncAttributeMaxDynamicSharedMemorySize,
                         SM_TOTAL);

    wa_prep<<<432, 256>>>(qkv_w, proj_w);
    wa_main<<<B, 256, SM_TOTAL>>>(x, qkv_b, proj_b, bias_table, rel_idx, out);
}